// round 3
// baseline (speedup 1.0000x reference)
#include <cuda_runtime.h>
#include <cstdint>

// out[c, i, j] = one_hot[i, c]      for c in [0,4)
// out[c, i, j] = one_hot[j, c-4]    for c in [4,8)
// one_hot: [L, 4] float32, L = 4096; out: [8, L, L] float32 (536.9 MB stores)
//
// R2: 75.5us, DRAM=74%, L1=70.6%, issue=50%. Loads + index math per single
// store are the residual overhead. R3: each thread covers an 8-row strip of
// one float4 column -> value loaded once, 8 streaming stores issued from
// registers. L1 load traffic /8, issue /~2.

#ifndef SEQEMB_BLOCK
#define SEQEMB_BLOCK 256
#endif
#define ROWS 8
#define MAX_L 4096

__device__ float g_oht[4][MAX_L];   // transposed one-hot, 64 KB scratch

__global__ void transpose_oh_kernel(const float* __restrict__ oh, int L)
{
    const int i = blockIdx.x * blockDim.x + threadIdx.x;
    if (i < L) {
        const float4 r = reinterpret_cast<const float4*>(oh)[i];  // row i of [L,4]
        g_oht[0][i] = r.x;
        g_oht[1][i] = r.y;
        g_oht[2][i] = r.z;
        g_oht[3][i] = r.w;
    }
}

__global__ __launch_bounds__(SEQEMB_BLOCK)
void seq_embed_kernel(const float* __restrict__ oh, float4* __restrict__ out, int L)
{
    const int c  = blockIdx.z;                                   // 0..7 plane
    const int i0 = blockIdx.y * ROWS;                            // row-strip base
    const int j4 = blockIdx.x * SEQEMB_BLOCK + threadIdx.x;      // float4 column
    const int L4 = L >> 2;
    if (j4 >= L4) return;

    float4* p = out + ((size_t)c * L + (size_t)i0) * (size_t)L4 + (size_t)j4;

    if (c < 4) {
        // row-constant broadcast: per-row scalar, loaded up front (L1 broadcast hits)
        float vals[ROWS];
#pragma unroll
        for (int r = 0; r < ROWS; r++)
            vals[r] = __ldg(&oh[(i0 + r) * 4 + c]);
#pragma unroll
        for (int r = 0; r < ROWS; r++) {
            __stcs(p, make_float4(vals[r], vals[r], vals[r], vals[r]));
            p += L4;
        }
    } else {
        // column one-hot: same float4 for every row in the strip -> load once
        const float4 v = *reinterpret_cast<const float4*>(&g_oht[c - 4][j4 << 2]);
#pragma unroll
        for (int r = 0; r < ROWS; r++) {
            __stcs(p, v);
            p += L4;
        }
    }
}

extern "C" void kernel_launch(void* const* d_in, const int* in_sizes, int n_in,
                              void* d_out, int out_size)
{
    const float* oh = (const float*)d_in[0];
    const int L = in_sizes[0] / 4;            // one_hot is [L, 4]
    const int L4 = L >> 2;

    transpose_oh_kernel<<<(L + 255) / 256, 256>>>(oh, L);

    dim3 block(SEQEMB_BLOCK);
    dim3 grid((L4 + SEQEMB_BLOCK - 1) / SEQEMB_BLOCK, L / ROWS, 8);
    seq_embed_kernel<<<grid, block>>>(oh, (float4*)d_out, L);
}